// round 8
// baseline (speedup 1.0000x reference)
#include <cuda_runtime.h>
#include <cuda_fp16.h>
#include <cstdint>

// ---------------------------------------------------------------------------
// TwinningEdgeAttention on GB300:
//   scatter-mean: fp16 tables via red.global.add.noftz.v4.f16x2 (at the ATOMG
//                 issue-floor; tables zero-initialized at load, re-zeroed by
//                 the MLP after consumption -> no zero_kernel launch)
//   MLP: fp16 HMMA, 1024 thr (lean regs), weights resident, tanh-sigmoid
// ---------------------------------------------------------------------------

#define MAXN 65536
#define DE   128

// zero-initialized at module load; fused_mlp restores zeros after each use
__device__ __align__(256) __half g_subj16[MAXN * DE];
__device__ __align__(256) __half g_obj16 [MAXN * DE];
__device__ float g_cnt_src[MAXN];
__device__ float g_cnt_dst[MAXN];
__device__ int   g_idx_is64;

// ========================= helpers =========================================

__device__ __forceinline__ uint32_t smem_u32(const void* p) {
    uint32_t a;
    asm("{ .reg .u64 t; cvta.to.shared.u64 t, %1; cvt.u32.u64 %0, t; }"
        : "=r"(a) : "l"(p));
    return a;
}

__device__ __forceinline__ uint32_t pack_f16(float lo, float hi) {
    uint32_t r;
    asm("cvt.rn.f16x2.f32 %0, %1, %2;" : "=r"(r) : "f"(hi), "f"(lo));
    return r;
}

__device__ __forceinline__ float tanh_approx(float x) {
    float r;
    asm("tanh.approx.f32 %0, %1;" : "=f"(r) : "f"(x));
    return r;
}

__device__ __forceinline__ void sts64(uint32_t addr, uint32_t a, uint32_t b) {
    asm volatile("st.shared.v2.b32 [%0], {%1,%2};" :: "r"(addr), "r"(a), "r"(b) : "memory");
}

__device__ __forceinline__ void sts128(uint32_t addr, uint32_t a, uint32_t b,
                                       uint32_t c, uint32_t d) {
    asm volatile("st.shared.v4.b32 [%0], {%1,%2,%3,%4};"
                 :: "r"(addr), "r"(a), "r"(b), "r"(c), "r"(d) : "memory");
}

__device__ __forceinline__ void ldm_x4(uint32_t addr, uint32_t* r) {
    asm volatile("ldmatrix.sync.aligned.m8n8.x4.shared.b16 {%0,%1,%2,%3}, [%4];"
                 : "=r"(r[0]), "=r"(r[1]), "=r"(r[2]), "=r"(r[3]) : "r"(addr));
}

__device__ __forceinline__ void ldm_x4_t(uint32_t addr, uint32_t* r) {
    asm volatile("ldmatrix.sync.aligned.m8n8.x4.trans.shared.b16 {%0,%1,%2,%3}, [%4];"
                 : "=r"(r[0]), "=r"(r[1]), "=r"(r[2]), "=r"(r[3]) : "r"(addr));
}

__device__ __forceinline__ void mma_f16(float* d, const uint32_t* a, const uint32_t* b) {
    asm volatile("mma.sync.aligned.m16n8k16.row.col.f32.f16.f16.f32 "
                 "{%0,%1,%2,%3}, {%4,%5,%6,%7}, {%8,%9}, {%0,%1,%2,%3};"
                 : "+f"(d[0]), "+f"(d[1]), "+f"(d[2]), "+f"(d[3])
                 : "r"(a[0]), "r"(a[1]), "r"(a[2]), "r"(a[3]), "r"(b[0]), "r"(b[1]));
}

__device__ __forceinline__ void red_v4h2(__half* p, uint32_t a, uint32_t b,
                                         uint32_t c, uint32_t d) {
    asm volatile("red.global.add.noftz.v4.f16x2 [%0], {%1,%2,%3,%4};"
                 :: "l"(p), "r"(a), "r"(b), "r"(c), "r"(d) : "memory");
}

// ========================= pre kernels =====================================

__global__ void detect_kernel(const int* __restrict__ ei_words) {
    if (threadIdx.x == 0) {
        int is64 = 1;
        for (int i = 0; i < 256; i++) {
            if (ei_words[2 * i + 1] != 0) { is64 = 0; break; }
        }
        g_idx_is64 = is64;
    }
}

// One warp per TWO edges: lanes 0-15 own edge0, lanes 16-31 own edge1.
__global__ void scatter_kernel(const float* __restrict__ ef,
                               const void* __restrict__ ei_raw, long long E) {
    long long gw = (long long)(blockIdx.x * blockDim.x + threadIdx.x) >> 5;
    int lane = threadIdx.x & 31;
    int half = lane >> 4;
    int grp  = lane & 15;
    long long edge = 2 * gw + half;
    if (edge >= E) return;

    long long s, d;
    if (g_idx_is64) {
        const long long* ei = (const long long*)ei_raw;
        s = ei[edge];
        d = ei[E + edge];
    } else {
        const int* ei = (const int*)ei_raw;
        s = ei[edge];
        d = ei[E + edge];
    }

    const float4* row = (const float4*)(ef + (size_t)edge * DE + grp * 8);
    float4 v0 = row[0];
    float4 v1 = row[1];
    uint32_t h0 = pack_f16(v0.x, v0.y);
    uint32_t h1 = pack_f16(v0.z, v0.w);
    uint32_t h2 = pack_f16(v1.x, v1.y);
    uint32_t h3 = pack_f16(v1.z, v1.w);

    red_v4h2(g_subj16 + (size_t)s * DE + grp * 8, h0, h1, h2, h3);
    red_v4h2(g_obj16  + (size_t)d * DE + grp * 8, h0, h1, h2, h3);

    if (grp == 0) {
        atomicAdd(&g_cnt_src[s], 1.0f);
        atomicAdd(&g_cnt_dst[d], 1.0f);
    }
}

// ========================= fp16 HMMA MLP (32 warps) ========================
// 1024 threads = 32 warps (8 m x 4 n), warp tile 16x32, CTA tile 128x128.
// After consuming each tile's table rows, re-zeroes them for the next launch.
// smem layout (bytes):
//   b1s[128]f32 @0, b2s[128]f32 @512
//   W1h fp16 [256][136] @2048    (69632)
//   W2h fp16 [128][136] @71680   (34816)
//   Hs  fp16 [128][136] @106496  (34816)
//   As  fp16 [128][264] @141312  (67584)  -> total 208896
static constexpr int OFF_B1 = 0, OFF_B2 = 512;
static constexpr int OFF_W1 = 2048, OFF_W2 = 71680, OFF_HS = 106496, OFF_AS = 141312;
static constexpr int LDW = 136, LDH = 136, LDA = 264;
static constexpr int SMEM_BYTES = 208896;

__global__ void __launch_bounds__(1024, 1)
fused_mlp(const float* __restrict__ W1, const float* __restrict__ b1,
          const float* __restrict__ W2, const float* __restrict__ b2,
          float* __restrict__ out, int n)
{
    extern __shared__ char smem[];
    const uint32_t sb = smem_u32(smem);
    const int tid = threadIdx.x, wid = tid >> 5, lane = tid & 31;

    float* b1s = (float*)(smem + OFF_B1);
    float* b2s = (float*)(smem + OFF_B2);

    const int warp_m = (wid & 7) * 16;    // 0..112
    const int warp_n = (wid >> 3) * 32;   // 0..96
    const int lm_row = lane & 15;
    const int lm_col = (lane >> 4) * 8;

    // ---- one-time: weights + biases -> smem (fp16) ----
    if (tid < 128) { b1s[tid] = b1[tid]; b2s[tid] = b2[tid]; }
    {
        int r = tid >> 3, c16 = tid & 7;           // 1024 thr: r 0..127, c16 0..7
#pragma unroll
        for (int blk = 0; blk < 2; blk++) {        // W1 rows [0,128) and [128,256)
            const float4* w = (const float4*)(W1 + (size_t)(blk * 128 + r) * 128 + c16 * 16);
            float4 w0 = w[0], w1 = w[1], w2 = w[2], w3 = w[3];
            sts128(sb + OFF_W1 + ((blk * 128 + r) * LDW + c16 * 16) * 2,
                   pack_f16(w0.x, w0.y), pack_f16(w0.z, w0.w),
                   pack_f16(w1.x, w1.y), pack_f16(w1.z, w1.w));
            sts128(sb + OFF_W1 + ((blk * 128 + r) * LDW + c16 * 16 + 8) * 2,
                   pack_f16(w2.x, w2.y), pack_f16(w2.z, w2.w),
                   pack_f16(w3.x, w3.y), pack_f16(w3.z, w3.w));
        }
        const float4* w = (const float4*)(W2 + (size_t)r * 128 + c16 * 16);
        float4 w0 = w[0], w1 = w[1], w2 = w[2], w3 = w[3];
        sts128(sb + OFF_W2 + (r * LDW + c16 * 16) * 2,
               pack_f16(w0.x, w0.y), pack_f16(w0.z, w0.w),
               pack_f16(w1.x, w1.y), pack_f16(w1.z, w1.w));
        sts128(sb + OFF_W2 + (r * LDW + c16 * 16 + 8) * 2,
               pack_f16(w2.x, w2.y), pack_f16(w2.z, w2.w),
               pack_f16(w3.x, w3.y), pack_f16(w3.z, w3.w));
    }

    const int TILES = (n + 127) >> 7;
    for (int tile = blockIdx.x; tile < TILES; tile += gridDim.x) {
        const int row0 = tile << 7;

        // ---- As fill: scaled means, fp16, [128][256] (LDA padded 264) ----
#pragma unroll
        for (int i = 0; i < 4; i++) {
            int idx = tid + 1024 * i;             // 0..4095
            int r = idx >> 5, c8 = idx & 31;      // r:0..127, c8:0..31
            int gr = row0 + r;
            uint32_t o0 = 0, o1 = 0, o2 = 0, o3 = 0;
            if (gr < n) {
                const __half* src;
                float cnt;
                if (c8 < 16) {
                    src = g_subj16 + (size_t)gr * DE + c8 * 8;
                    cnt = g_cnt_src[gr];
                } else {
                    src = g_obj16 + (size_t)gr * DE + (c8 - 16) * 8;
                    cnt = g_cnt_dst[gr];
                }
                float s = 1.f / fmaxf(cnt, 1.f);
                uint4 raw = *(const uint4*)src;
                const __half2* h2 = (const __half2*)&raw;
                float2 f0 = __half22float2(h2[0]);
                float2 f1 = __half22float2(h2[1]);
                float2 f2 = __half22float2(h2[2]);
                float2 f3 = __half22float2(h2[3]);
                o0 = pack_f16(f0.x * s, f0.y * s);
                o1 = pack_f16(f1.x * s, f1.y * s);
                o2 = pack_f16(f2.x * s, f2.y * s);
                o3 = pack_f16(f3.x * s, f3.y * s);
            }
            sts128(sb + OFF_AS + (r * LDA + c8 * 8) * 2, o0, o1, o2, o3);
        }
        __syncthreads();

        // ---- re-zero consumed table rows + counts (overlaps phase 1) ----
        {
            const uint4 z = make_uint4(0, 0, 0, 0);
#pragma unroll
            for (int i = 0; i < 4; i++) {
                int idx = tid + 1024 * i;
                int r = idx >> 5, c8 = idx & 31;
                int gr = row0 + r;
                if (gr < n) {
                    __half* dst = (c8 < 16)
                        ? g_subj16 + (size_t)gr * DE + c8 * 8
                        : g_obj16  + (size_t)gr * DE + (c8 - 16) * 8;
                    *(uint4*)dst = z;
                }
            }
            if (tid < 128) {
                int gr = row0 + tid;
                if (gr < n) { g_cnt_src[gr] = 0.f; g_cnt_dst[gr] = 0.f; }
            }
        }

        // ============ phase 1: As[128x256] @ W1 -> P ======================
        float P[4][4];
#pragma unroll
        for (int j = 0; j < 4; j++)
#pragma unroll
            for (int k = 0; k < 4; k++) P[j][k] = 0.f;

#pragma unroll
        for (int ks = 0; ks < 16; ks++) {
            uint32_t a[4], bq[2][4];
            ldm_x4(sb + OFF_AS + ((warp_m + lm_row) * LDA + ks * 16 + lm_col) * 2, a);
#pragma unroll
            for (int tb = 0; tb < 2; tb++)
                ldm_x4_t(sb + OFF_W1 + ((ks * 16 + lm_row) * LDW + warp_n + tb * 16 + lm_col) * 2, bq[tb]);
#pragma unroll
            for (int tn = 0; tn < 4; tn++)
                mma_f16(P[tn], a, &bq[tn >> 1][(tn & 1) * 2]);
        }

        // ---- epilogue 1: relu(P + b1) -> Hs (fp16) ----
        {
            int r0 = warp_m + (lane >> 2), r1 = r0 + 8;
            int cb = warp_n + (lane & 3) * 2;
#pragma unroll
            for (int tn = 0; tn < 4; tn++) {
                int col = cb + tn * 8;
                float x0 = fmaxf(P[tn][0] + b1s[col],     0.f);
                float x1 = fmaxf(P[tn][1] + b1s[col + 1], 0.f);
                float x2 = fmaxf(P[tn][2] + b1s[col],     0.f);
                float x3 = fmaxf(P[tn][3] + b1s[col + 1], 0.f);
                *(uint32_t*)(smem + OFF_HS + (r0 * LDH + col) * 2) = pack_f16(x0, x1);
                *(uint32_t*)(smem + OFF_HS + (r1 * LDH + col) * 2) = pack_f16(x2, x3);
            }
        }
        __syncthreads();

        // ============ phase 2: Hs[128x128] @ W2 -> P ======================
#pragma unroll
        for (int j = 0; j < 4; j++)
#pragma unroll
            for (int k = 0; k < 4; k++) P[j][k] = 0.f;

#pragma unroll
        for (int ks = 0; ks < 8; ks++) {
            uint32_t a[4], bq[2][4];
            ldm_x4(sb + OFF_HS + ((warp_m + lm_row) * LDH + ks * 16 + lm_col) * 2, a);
#pragma unroll
            for (int tb = 0; tb < 2; tb++)
                ldm_x4_t(sb + OFF_W2 + ((ks * 16 + lm_row) * LDW + warp_n + tb * 16 + lm_col) * 2, bq[tb]);
#pragma unroll
            for (int tn = 0; tn < 4; tn++)
                mma_f16(P[tn], a, &bq[tn >> 1][(tn & 1) * 2]);
        }

        // ---- epilogue 2: sigmoid via tanh -> gmem ----
        {
            int r0 = warp_m + (lane >> 2), r1 = r0 + 8;
            int cb = warp_n + (lane & 3) * 2;
            int gr0 = row0 + r0, gr1 = row0 + r1;
#pragma unroll
            for (int tn = 0; tn < 4; tn++) {
                int col = cb + tn * 8;
                if (gr0 < n) {
                    float2 o;
                    o.x = fmaf(0.5f, tanh_approx(0.5f * (P[tn][0] + b2s[col])),     0.5f);
                    o.y = fmaf(0.5f, tanh_approx(0.5f * (P[tn][1] + b2s[col + 1])), 0.5f);
                    *(float2*)(out + (size_t)gr0 * 128 + col) = o;
                }
                if (gr1 < n) {
                    float2 o;
                    o.x = fmaf(0.5f, tanh_approx(0.5f * (P[tn][2] + b2s[col])),     0.5f);
                    o.y = fmaf(0.5f, tanh_approx(0.5f * (P[tn][3] + b2s[col + 1])), 0.5f);
                    *(float2*)(out + (size_t)gr1 * 128 + col) = o;
                }
            }
        }
        __syncthreads();   // As/Hs free for next tile
    }
}

// ========================= launch ==========================================

extern "C" void kernel_launch(void* const* d_in, const int* in_sizes, int n_in,
                              void* d_out, int out_size) {
    const float* ef = (const float*)d_in[0];
    const float* W1 = (const float*)d_in[1];
    const float* b1 = (const float*)d_in[2];
    const float* W2 = (const float*)d_in[3];
    const float* b2 = (const float*)d_in[4];
    const void*  ei = d_in[5];

    long long E = in_sizes[5] / 2;
    int n = out_size / 128;

    detect_kernel<<<1, 32>>>((const int*)ei);

    long long warps = (E + 1) / 2;
    int sblocks = (int)((warps * 32 + 255) / 256);
    scatter_kernel<<<sblocks, 256>>>(ef, ei, E);

    cudaFuncSetAttribute(fused_mlp, cudaFuncAttributeMaxDynamicSharedMemorySize, SMEM_BYTES);
    int TILES = (n + 127) / 128;
    int grid = TILES < 148 ? TILES : 148;
    fused_mlp<<<grid, 1024, SMEM_BYTES>>>(W1, b1, W2, b2, (float*)d_out, n);
}

// round 9
// speedup vs baseline: 1.0493x; 1.0493x over previous
#include <cuda_runtime.h>
#include <cuda_fp16.h>
#include <cstdint>

// ---------------------------------------------------------------------------
// TwinningEdgeAttention on GB300:
//   scatter-mean: fp16 tables via red.global.add.noftz.v4.f16x2 (REDG floor)
//   MLP: fp16 HMMA, 1024 thr, weights resident, cp.async As prefetch hidden
//        behind phase 2 (single buffer), deferred mean-scaling, tanh-sigmoid
// ---------------------------------------------------------------------------

#define MAXN 65536
#define DE   128

__device__ __align__(256) __half g_subj16[MAXN * DE];
__device__ __align__(256) __half g_obj16 [MAXN * DE];
__device__ float g_cnt_src[MAXN];
__device__ float g_cnt_dst[MAXN];
__device__ int   g_idx_is64;

// ========================= helpers =========================================

__device__ __forceinline__ uint32_t smem_u32(const void* p) {
    uint32_t a;
    asm("{ .reg .u64 t; cvta.to.shared.u64 t, %1; cvt.u32.u64 %0, t; }"
        : "=r"(a) : "l"(p));
    return a;
}

__device__ __forceinline__ uint32_t pack_f16(float lo, float hi) {
    uint32_t r;
    asm("cvt.rn.f16x2.f32 %0, %1, %2;" : "=r"(r) : "f"(hi), "f"(lo));
    return r;
}

__device__ __forceinline__ float tanh_approx(float x) {
    float r;
    asm("tanh.approx.f32 %0, %1;" : "=f"(r) : "f"(x));
    return r;
}

__device__ __forceinline__ void sts128(uint32_t addr, uint32_t a, uint32_t b,
                                       uint32_t c, uint32_t d) {
    asm volatile("st.shared.v4.b32 [%0], {%1,%2,%3,%4};"
                 :: "r"(addr), "r"(a), "r"(b), "r"(c), "r"(d) : "memory");
}

__device__ __forceinline__ void ldm_x4(uint32_t addr, uint32_t* r) {
    asm volatile("ldmatrix.sync.aligned.m8n8.x4.shared.b16 {%0,%1,%2,%3}, [%4];"
                 : "=r"(r[0]), "=r"(r[1]), "=r"(r[2]), "=r"(r[3]) : "r"(addr));
}

__device__ __forceinline__ void ldm_x4_t(uint32_t addr, uint32_t* r) {
    asm volatile("ldmatrix.sync.aligned.m8n8.x4.trans.shared.b16 {%0,%1,%2,%3}, [%4];"
                 : "=r"(r[0]), "=r"(r[1]), "=r"(r[2]), "=r"(r[3]) : "r"(addr));
}

__device__ __forceinline__ void mma_f16(float* d, const uint32_t* a, const uint32_t* b) {
    asm volatile("mma.sync.aligned.m16n8k16.row.col.f32.f16.f16.f32 "
                 "{%0,%1,%2,%3}, {%4,%5,%6,%7}, {%8,%9}, {%0,%1,%2,%3};"
                 : "+f"(d[0]), "+f"(d[1]), "+f"(d[2]), "+f"(d[3])
                 : "r"(a[0]), "r"(a[1]), "r"(a[2]), "r"(a[3]), "r"(b[0]), "r"(b[1]));
}

__device__ __forceinline__ void red_v4h2(__half* p, uint32_t a, uint32_t b,
                                         uint32_t c, uint32_t d) {
    asm volatile("red.global.add.noftz.v4.f16x2 [%0], {%1,%2,%3,%4};"
                 :: "l"(p), "r"(a), "r"(b), "r"(c), "r"(d) : "memory");
}

__device__ __forceinline__ void cp16(uint32_t dst, const void* src, int srcsize) {
    asm volatile("cp.async.cg.shared.global [%0], [%1], 16, %2;"
                 :: "r"(dst), "l"(src), "r"(srcsize) : "memory");
}
#define CP_COMMIT() asm volatile("cp.async.commit_group;" ::: "memory")
#define CP_WAIT0()  asm volatile("cp.async.wait_group 0;" ::: "memory")

// ========================= pre kernels =====================================

// zero tables + counts; block 0 thread 0 also sniffs the index dtype
__global__ void zero_kernel(int n, const int* __restrict__ ei_words) {
    if (blockIdx.x == 0 && threadIdx.x == 0) {
        int is64 = 1;
        for (int i = 0; i < 256; i++) {
            if (ei_words[2 * i + 1] != 0) { is64 = 0; break; }
        }
        g_idx_is64 = is64;
    }
    const uint4 z = make_uint4(0, 0, 0, 0);
    int total16 = n * (DE / 8);
    int stride = gridDim.x * blockDim.x;
    for (int i = blockIdx.x * blockDim.x + threadIdx.x; i < total16; i += stride) {
        reinterpret_cast<uint4*>(g_subj16)[i] = z;
        reinterpret_cast<uint4*>(g_obj16)[i]  = z;
    }
    for (int i = blockIdx.x * blockDim.x + threadIdx.x; i < n; i += stride) {
        g_cnt_src[i] = 0.f;
        g_cnt_dst[i] = 0.f;
    }
}

// One warp per TWO edges: lanes 0-15 own edge0, lanes 16-31 own edge1.
__global__ void scatter_kernel(const float* __restrict__ ef,
                               const void* __restrict__ ei_raw, long long E) {
    long long gw = (long long)(blockIdx.x * blockDim.x + threadIdx.x) >> 5;
    int lane = threadIdx.x & 31;
    int half = lane >> 4;
    int grp  = lane & 15;
    long long edge = 2 * gw + half;
    if (edge >= E) return;

    long long s, d;
    if (g_idx_is64) {
        const long long* ei = (const long long*)ei_raw;
        s = ei[edge];
        d = ei[E + edge];
    } else {
        const int* ei = (const int*)ei_raw;
        s = ei[edge];
        d = ei[E + edge];
    }

    const float4* row = (const float4*)(ef + (size_t)edge * DE + grp * 8);
    float4 v0 = row[0];
    float4 v1 = row[1];
    uint32_t h0 = pack_f16(v0.x, v0.y);
    uint32_t h1 = pack_f16(v0.z, v0.w);
    uint32_t h2 = pack_f16(v1.x, v1.y);
    uint32_t h3 = pack_f16(v1.z, v1.w);

    red_v4h2(g_subj16 + (size_t)s * DE + grp * 8, h0, h1, h2, h3);
    red_v4h2(g_obj16  + (size_t)d * DE + grp * 8, h0, h1, h2, h3);

    if (grp == 0) {
        atomicAdd(&g_cnt_src[s], 1.0f);
        atomicAdd(&g_cnt_dst[d], 1.0f);
    }
}

// ========================= fp16 HMMA MLP (32 warps) ========================
// 1024 threads = 32 warps (8 m x 4 n), warp tile 16x32, CTA tile 128x128.
// As holds RAW fp16 sums (cp.async); scaling deferred to epilogue 1 via
// dual accumulators. As prefetch for tile t+1 overlaps phase 2 of tile t.
// smem layout (bytes):
//   b1s[128]f32 @0, b2s[128]f32 @512
//   W1h fp16 [256][136] @2048    (69632)
//   W2h fp16 [128][136] @71680   (34816)
//   Hs  fp16 [128][136] @106496  (34816)
//   As  fp16 [128][264] @141312  (67584)  -> total 208896
static constexpr int OFF_B1 = 0, OFF_B2 = 512;
static constexpr int OFF_W1 = 2048, OFF_W2 = 71680, OFF_HS = 106496, OFF_AS = 141312;
static constexpr int LDW = 136, LDH = 136, LDA = 264;
static constexpr int SMEM_BYTES = 208896;

__device__ __forceinline__ void prefetch_as(uint32_t asb, int row0, int n, int tid) {
#pragma unroll
    for (int i = 0; i < 4; i++) {
        int idx = tid + 1024 * i;             // 0..4095
        int r = idx >> 5, c8 = idx & 31;      // r:0..127, c8:0..31
        int gr = row0 + r;
        const __half* src = (c8 < 16)
            ? g_subj16 + (size_t)gr * DE + c8 * 8
            : g_obj16  + (size_t)gr * DE + (c8 - 16) * 8;
        int sz = (gr < n) ? 16 : 0;
        cp16(asb + (r * LDA + c8 * 8) * 2, src, sz);
    }
}

__global__ void __launch_bounds__(1024, 1)
fused_mlp(const float* __restrict__ W1, const float* __restrict__ b1,
          const float* __restrict__ W2, const float* __restrict__ b2,
          float* __restrict__ out, int n)
{
    extern __shared__ char smem[];
    const uint32_t sb = smem_u32(smem);
    const int tid = threadIdx.x, wid = tid >> 5, lane = tid & 31;

    float* b1s = (float*)(smem + OFF_B1);
    float* b2s = (float*)(smem + OFF_B2);

    const int warp_m = (wid & 7) * 16;    // 0..112
    const int warp_n = (wid >> 3) * 32;   // 0..96
    const int lm_row = lane & 15;
    const int lm_col = (lane >> 4) * 8;

    const int TILES = (n + 127) >> 7;

    // ---- prefetch first tile's As (raw fp16 sums) ----
    if (blockIdx.x < TILES)
        prefetch_as(sb + OFF_AS, blockIdx.x << 7, n, tid);
    CP_COMMIT();

    // ---- one-time: weights + biases -> smem (fp16) ----
    if (tid < 128) { b1s[tid] = b1[tid]; b2s[tid] = b2[tid]; }
    {
        int r = tid >> 3, c16 = tid & 7;
#pragma unroll
        for (int blk = 0; blk < 2; blk++) {
            const float4* w = (const float4*)(W1 + (size_t)(blk * 128 + r) * 128 + c16 * 16);
            float4 w0 = w[0], w1 = w[1], w2 = w[2], w3 = w[3];
            sts128(sb + OFF_W1 + ((blk * 128 + r) * LDW + c16 * 16) * 2,
                   pack_f16(w0.x, w0.y), pack_f16(w0.z, w0.w),
                   pack_f16(w1.x, w1.y), pack_f16(w1.z, w1.w));
            sts128(sb + OFF_W1 + ((blk * 128 + r) * LDW + c16 * 16 + 8) * 2,
                   pack_f16(w2.x, w2.y), pack_f16(w2.z, w2.w),
                   pack_f16(w3.x, w3.y), pack_f16(w3.z, w3.w));
        }
        const float4* w = (const float4*)(W2 + (size_t)r * 128 + c16 * 16);
        float4 w0 = w[0], w1 = w[1], w2 = w[2], w3 = w[3];
        sts128(sb + OFF_W2 + (r * LDW + c16 * 16) * 2,
               pack_f16(w0.x, w0.y), pack_f16(w0.z, w0.w),
               pack_f16(w1.x, w1.y), pack_f16(w1.z, w1.w));
        sts128(sb + OFF_W2 + (r * LDW + c16 * 16 + 8) * 2,
               pack_f16(w2.x, w2.y), pack_f16(w2.z, w2.w),
               pack_f16(w3.x, w3.y), pack_f16(w3.z, w3.w));
    }

    for (int tile = blockIdx.x; tile < TILES; tile += gridDim.x) {
        const int row0 = tile << 7;

        CP_WAIT0();            // As for this tile landed
        __syncthreads();       // + weights (first iter) + prev Hs reads done

        // ============ phase 1: As[128x256] @ W1 -> P1 (subj) / P2 (obj) ===
        float P1[4][4], P2[4][4];
#pragma unroll
        for (int j = 0; j < 4; j++)
#pragma unroll
            for (int k = 0; k < 4; k++) { P1[j][k] = 0.f; P2[j][k] = 0.f; }

#pragma unroll
        for (int ks = 0; ks < 16; ks++) {
            uint32_t a[4], bq[2][4];
            ldm_x4(sb + OFF_AS + ((warp_m + lm_row) * LDA + ks * 16 + lm_col) * 2, a);
#pragma unroll
            for (int tb = 0; tb < 2; tb++)
                ldm_x4_t(sb + OFF_W1 + ((ks * 16 + lm_row) * LDW + warp_n + tb * 16 + lm_col) * 2, bq[tb]);
            float (*acc)[4] = (ks < 8) ? P1 : P2;
#pragma unroll
            for (int tn = 0; tn < 4; tn++)
                mma_f16(acc[tn], a, &bq[tn >> 1][(tn & 1) * 2]);
        }

        // ---- epilogue 1: relu(invs*P1 + invo*P2 + b1) -> Hs (fp16) ----
        {
            int r0 = warp_m + (lane >> 2), r1 = r0 + 8;
            int gr0 = row0 + r0, gr1 = row0 + r1;
            float is0 = 0.f, io0 = 0.f, is1 = 0.f, io1 = 0.f;
            if (gr0 < n) {
                is0 = 1.f / fmaxf(g_cnt_src[gr0], 1.f);
                io0 = 1.f / fmaxf(g_cnt_dst[gr0], 1.f);
            }
            if (gr1 < n) {
                is1 = 1.f / fmaxf(g_cnt_src[gr1], 1.f);
                io1 = 1.f / fmaxf(g_cnt_dst[gr1], 1.f);
            }
            int cb = warp_n + (lane & 3) * 2;
#pragma unroll
            for (int tn = 0; tn < 4; tn++) {
                int col = cb + tn * 8;
                float x0 = fmaxf(fmaf(is0, P1[tn][0], fmaf(io0, P2[tn][0], b1s[col])),     0.f);
                float x1 = fmaxf(fmaf(is0, P1[tn][1], fmaf(io0, P2[tn][1], b1s[col + 1])), 0.f);
                float x2 = fmaxf(fmaf(is1, P1[tn][2], fmaf(io1, P2[tn][2], b1s[col])),     0.f);
                float x3 = fmaxf(fmaf(is1, P1[tn][3], fmaf(io1, P2[tn][3], b1s[col + 1])), 0.f);
                *(uint32_t*)(smem + OFF_HS + (r0 * LDH + col) * 2) = pack_f16(x0, x1);
                *(uint32_t*)(smem + OFF_HS + (r1 * LDH + col) * 2) = pack_f16(x2, x3);
            }
        }
        __syncthreads();       // Hs visible; all phase-1 As reads complete

        // ---- prefetch next tile's As (overlaps phase 2 + epilogue 2) ----
        {
            int ntile = tile + gridDim.x;
            if (ntile < TILES)
                prefetch_as(sb + OFF_AS, ntile << 7, n, tid);
            CP_COMMIT();
        }

        // ============ phase 2: Hs[128x128] @ W2 -> P1 ======================
#pragma unroll
        for (int j = 0; j < 4; j++)
#pragma unroll
            for (int k = 0; k < 4; k++) P1[j][k] = 0.f;

#pragma unroll
        for (int ks = 0; ks < 8; ks++) {
            uint32_t a[4], bq[2][4];
            ldm_x4(sb + OFF_HS + ((warp_m + lm_row) * LDH + ks * 16 + lm_col) * 2, a);
#pragma unroll
            for (int tb = 0; tb < 2; tb++)
                ldm_x4_t(sb + OFF_W2 + ((ks * 16 + lm_row) * LDW + warp_n + tb * 16 + lm_col) * 2, bq[tb]);
#pragma unroll
            for (int tn = 0; tn < 4; tn++)
                mma_f16(P1[tn], a, &bq[tn >> 1][(tn & 1) * 2]);
        }

        // ---- epilogue 2: sigmoid via tanh -> gmem ----
        {
            int r0 = warp_m + (lane >> 2), r1 = r0 + 8;
            int cb = warp_n + (lane & 3) * 2;
            int gr0 = row0 + r0, gr1 = row0 + r1;
#pragma unroll
            for (int tn = 0; tn < 4; tn++) {
                int col = cb + tn * 8;
                if (gr0 < n) {
                    float2 o;
                    o.x = fmaf(0.5f, tanh_approx(0.5f * (P1[tn][0] + b2s[col])),     0.5f);
                    o.y = fmaf(0.5f, tanh_approx(0.5f * (P1[tn][1] + b2s[col + 1])), 0.5f);
                    *(float2*)(out + (size_t)gr0 * 128 + col) = o;
                }
                if (gr1 < n) {
                    float2 o;
                    o.x = fmaf(0.5f, tanh_approx(0.5f * (P1[tn][2] + b2s[col])),     0.5f);
                    o.y = fmaf(0.5f, tanh_approx(0.5f * (P1[tn][3] + b2s[col + 1])), 0.5f);
                    *(float2*)(out + (size_t)gr1 * 128 + col) = o;
                }
            }
        }
        // no trailing sync: loop-top CP_WAIT0 + __syncthreads covers reuse
    }
}

// ========================= launch ==========================================

extern "C" void kernel_launch(void* const* d_in, const int* in_sizes, int n_in,
                              void* d_out, int out_size) {
    const float* ef = (const float*)d_in[0];
    const float* W1 = (const float*)d_in[1];
    const float* b1 = (const float*)d_in[2];
    const float* W2 = (const float*)d_in[3];
    const float* b2 = (const float*)d_in[4];
    const void*  ei = d_in[5];

    long long E = in_sizes[5] / 2;
    int n = out_size / 128;

    zero_kernel<<<1024, 256>>>(n, (const int*)ei);

    long long warps = (E + 1) / 2;
    int sblocks = (int)((warps * 32 + 255) / 256);
    scatter_kernel<<<sblocks, 256>>>(ef, ei, E);

    cudaFuncSetAttribute(fused_mlp, cudaFuncAttributeMaxDynamicSharedMemorySize, SMEM_BYTES);
    int TILES = (n + 127) / 128;
    int grid = TILES < 148 ? TILES : 148;
    fused_mlp<<<grid, 1024, SMEM_BYTES>>>(W1, b1, W2, b2, (float*)d_out, n);
}